// round 3
// baseline (speedup 1.0000x reference)
#include <cuda_runtime.h>
#include <math.h>

#define NN    50000
#define EE    800000
#define FIN   256
#define HID   64
#define HEADS 4
#define CLS   32
#define ETOT  (EE + NN)
#define NEG_SLOPE 0.2f

// ---------------- scratch (device globals; no allocation allowed) ----------
__device__ float    g_h1[NN * 256];        // layer-1 linear output  [N,4,64]
__device__ float    g_as1[NN * 4];         // a_src layer1
__device__ float    g_ad1[NN * 4];         // a_dst layer1
__device__ unsigned g_emax1[NN * 4];       // ordered-encoded segment max
__device__ float    g_esum1[NN * 4];
__device__ float    g_eexp1[ETOT * 4];     // per-edge exp values
__device__ float    g_agg1[NN * 256];      // layer-1 aggregated (pre-relu)
__device__ float    g_h2[NN * 32];         // layer-2 linear output
__device__ float    g_as2[NN];
__device__ float    g_ad2[NN];
__device__ unsigned g_emax2[NN];
__device__ float    g_esum2[NN];
__device__ float    g_eexp2[ETOT];
__device__ float    g_out2[NN * 32];       // layer-2 aggregated

// ---------------- ordered-float <-> uint for atomicMax ---------------------
__device__ __forceinline__ unsigned f2u_ord(float f) {
    unsigned u = __float_as_uint(f);
    return (u & 0x80000000u) ? ~u : (u | 0x80000000u);
}
__device__ __forceinline__ float u2f_ord(unsigned u) {
    return (u & 0x80000000u) ? __uint_as_float(u & 0x7FFFFFFFu)
                             : __uint_as_float(~u);
}
#define ENC_NEG_INF 0x007FFFFFu   // f2u_ord(-inf)

// ---------------- init ------------------------------------------------------
__global__ void k_init(int n) {
    int stride = gridDim.x * blockDim.x;
    int t = blockIdx.x * blockDim.x + threadIdx.x;
    for (int i = t; i < n * 256; i += stride) g_agg1[i] = 0.f;
    for (int i = t; i < n * 32;  i += stride) g_out2[i] = 0.f;
    for (int i = t; i < n * 4;   i += stride) { g_emax1[i] = ENC_NEG_INF; g_esum1[i] = 0.f; }
    for (int i = t; i < n;       i += stride) { g_emax2[i] = ENC_NEG_INF; g_esum2[i] = 0.f; }
}

// ---------------- GEMM1: [M,256] @ [256,256] -> g_h1 ------------------------
#define G1_BM 64
#define G1_BN 64
#define G1_BK 16
__global__ void k_gemm1(const float* __restrict__ A, const float* __restrict__ B, int M) {
    __shared__ float As[G1_BK][G1_BM + 4];
    __shared__ float Bs[G1_BK][G1_BN + 4];
    int tid = threadIdx.x;
    int tx = tid % 16, ty = tid / 16;
    int row0 = blockIdx.y * G1_BM, col0 = blockIdx.x * G1_BN;
    float acc[4][4] = {};
    for (int k0 = 0; k0 < 256; k0 += G1_BK) {
        #pragma unroll
        for (int i = 0; i < 4; i++) {
            int idx = tid + i * 256;
            int m = idx / G1_BK, k = idx % G1_BK;
            int gr = row0 + m;
            As[k][m] = (gr < M) ? A[gr * 256 + k0 + k] : 0.f;
        }
        #pragma unroll
        for (int i = 0; i < 4; i++) {
            int idx = tid + i * 256;
            int k = idx / G1_BN, nn = idx % G1_BN;
            Bs[k][nn] = B[(k0 + k) * 256 + col0 + nn];
        }
        __syncthreads();
        #pragma unroll
        for (int kk = 0; kk < G1_BK; kk++) {
            float a[4], b[4];
            #pragma unroll
            for (int i = 0; i < 4; i++) a[i] = As[kk][ty * 4 + i];
            #pragma unroll
            for (int j = 0; j < 4; j++) b[j] = Bs[kk][tx * 4 + j];
            #pragma unroll
            for (int i = 0; i < 4; i++)
                #pragma unroll
                for (int j = 0; j < 4; j++) acc[i][j] += a[i] * b[j];
        }
        __syncthreads();
    }
    #pragma unroll
    for (int i = 0; i < 4; i++) {
        int gr = row0 + ty * 4 + i;
        if (gr < M) {
            #pragma unroll
            for (int j = 0; j < 4; j++)
                g_h1[gr * 256 + col0 + tx * 4 + j] = acc[i][j];
        }
    }
}

// ---------------- attention dots, layer 1 (warp per node) -------------------
__global__ void k_attn1(const float* __restrict__ att_src, const float* __restrict__ att_dst, int n) {
    int warp = (blockIdx.x * blockDim.x + threadIdx.x) >> 5;
    int lane = threadIdx.x & 31;
    if (warp >= n) return;
    const float4* hr = (const float4*)(g_h1 + (size_t)warp * 256);
    const float4* sa = (const float4*)att_src;   // 256 floats flat = col index
    const float4* da = (const float4*)att_dst;
    float4 v0 = hr[lane], v1 = hr[lane + 32];
    float4 s0 = sa[lane], s1 = sa[lane + 32];
    float4 d0 = da[lane], d1 = da[lane + 32];
    float ps0 = v0.x*s0.x + v0.y*s0.y + v0.z*s0.z + v0.w*s0.w;
    float ps1 = v1.x*s1.x + v1.y*s1.y + v1.z*s1.z + v1.w*s1.w;
    float pd0 = v0.x*d0.x + v0.y*d0.y + v0.z*d0.z + v0.w*d0.w;
    float pd1 = v1.x*d1.x + v1.y*d1.y + v1.z*d1.z + v1.w*d1.w;
    #pragma unroll
    for (int off = 1; off < 16; off <<= 1) {
        ps0 += __shfl_xor_sync(0xffffffffu, ps0, off);
        ps1 += __shfl_xor_sync(0xffffffffu, ps1, off);
        pd0 += __shfl_xor_sync(0xffffffffu, pd0, off);
        pd1 += __shfl_xor_sync(0xffffffffu, pd1, off);
    }
    if (lane == 0)  { g_as1[warp*4+0] = ps0; g_as1[warp*4+2] = ps1;
                      g_ad1[warp*4+0] = pd0; g_ad1[warp*4+2] = pd1; }
    if (lane == 16) { g_as1[warp*4+1] = ps0; g_as1[warp*4+3] = ps1;
                      g_ad1[warp*4+1] = pd0; g_ad1[warp*4+3] = pd1; }
}

// ---------------- edge helpers ---------------------------------------------
// edge_index arrives as int32 (harness converts int64 -> int32)
__device__ __forceinline__ void edge_sd(const int* __restrict__ ei, int e, int E, int& s, int& d) {
    if (e < E) { s = ei[e]; d = ei[E + e]; }
    else       { s = d = e - E; }
}

// pass A: segment max (layer 1): one thread per (edge, head)
__global__ void k_edgeA1(const int* __restrict__ ei, int E, int etot) {
    int idx = blockIdx.x * blockDim.x + threadIdx.x;
    if (idx >= etot * 4) return;
    int e = idx >> 2, h = idx & 3;
    int s, d; edge_sd(ei, e, E, s, d);
    float v = g_as1[s * 4 + h] + g_ad1[d * 4 + h];
    v = (v > 0.f) ? v : NEG_SLOPE * v;
    atomicMax(&g_emax1[d * 4 + h], f2u_ord(v));
}

// pass B: exp + segment sum (layer 1)
__global__ void k_edgeB1(const int* __restrict__ ei, int E, int etot) {
    int idx = blockIdx.x * blockDim.x + threadIdx.x;
    if (idx >= etot * 4) return;
    int e = idx >> 2, h = idx & 3;
    int s, d; edge_sd(ei, e, E, s, d);
    float v = g_as1[s * 4 + h] + g_ad1[d * 4 + h];
    v = (v > 0.f) ? v : NEG_SLOPE * v;
    float m  = u2f_ord(g_emax1[d * 4 + h]);
    float ex = __expf(v - m);
    g_eexp1[idx] = ex;
    atomicAdd(&g_esum1[d * 4 + h], ex);
}

// pass C: aggregate messages (layer 1): one warp per edge, 256 channels
__global__ void k_edgeC1(const int* __restrict__ ei, int E, int etot) {
    int warp = (blockIdx.x * blockDim.x + threadIdx.x) >> 5;
    int lane = threadIdx.x & 31;
    if (warp >= etot) return;
    int s, d; edge_sd(ei, warp, E, s, d);
    int h0 = lane >> 4;          // head for cols [4*lane, 4*lane+3]
    int h1 = 2 + (lane >> 4);    // head for cols [128+4*lane, ...]
    float al0 = g_eexp1[warp * 4 + h0] / (g_esum1[d * 4 + h0] + 1e-16f);
    float al1 = g_eexp1[warp * 4 + h1] / (g_esum1[d * 4 + h1] + 1e-16f);
    const float4* hs = (const float4*)(g_h1 + (size_t)s * 256);
    float4 v0 = hs[lane], v1 = hs[lane + 32];
    float* op = g_agg1 + (size_t)d * 256;
    atomicAdd(op + 4*lane + 0, v0.x * al0);
    atomicAdd(op + 4*lane + 1, v0.y * al0);
    atomicAdd(op + 4*lane + 2, v0.z * al0);
    atomicAdd(op + 4*lane + 3, v0.w * al0);
    atomicAdd(op + 128 + 4*lane + 0, v1.x * al1);
    atomicAdd(op + 128 + 4*lane + 1, v1.y * al1);
    atomicAdd(op + 128 + 4*lane + 2, v1.z * al1);
    atomicAdd(op + 128 + 4*lane + 3, v1.w * al1);
}

// ---------------- GEMM2: relu(agg1 + b1) @ W2 -> g_h2  [M,256]@[256,32] -----
#define G2_BM 128
#define G2_BN 32
#define G2_BK 32
__global__ void k_gemm2(const float* __restrict__ b1, const float* __restrict__ W2, int M) {
    __shared__ float As[G2_BK][G2_BM + 4];
    __shared__ float Bs[G2_BK][G2_BN + 2];
    int tid = threadIdx.x;
    int tx = tid % 8, ty = tid / 8;       // 8 x 32 thread grid, 4x4 micro-tile
    int row0 = blockIdx.y * G2_BM;
    float acc[4][4] = {};
    for (int k0 = 0; k0 < 256; k0 += G2_BK) {
        #pragma unroll
        for (int i = 0; i < 16; i++) {
            int idx = tid + i * 256;
            int m = idx / G2_BK, k = idx % G2_BK;
            int gr = row0 + m;
            float v = 0.f;
            if (gr < M) {
                v = g_agg1[(size_t)gr * 256 + k0 + k] + b1[k0 + k];
                v = fmaxf(v, 0.f);          // fused bias + relu
            }
            As[k][m] = v;
        }
        #pragma unroll
        for (int i = 0; i < 4; i++) {
            int idx = tid + i * 256;
            int k = idx / G2_BN, nn = idx % G2_BN;
            Bs[k][nn] = W2[(k0 + k) * 32 + nn];
        }
        __syncthreads();
        #pragma unroll
        for (int kk = 0; kk < G2_BK; kk++) {
            float a[4], b[4];
            #pragma unroll
            for (int i = 0; i < 4; i++) a[i] = As[kk][ty * 4 + i];
            #pragma unroll
            for (int j = 0; j < 4; j++) b[j] = Bs[kk][tx * 4 + j];
            #pragma unroll
            for (int i = 0; i < 4; i++)
                #pragma unroll
                for (int j = 0; j < 4; j++) acc[i][j] += a[i] * b[j];
        }
        __syncthreads();
    }
    #pragma unroll
    for (int i = 0; i < 4; i++) {
        int gr = row0 + ty * 4 + i;
        if (gr < M) {
            #pragma unroll
            for (int j = 0; j < 4; j++)
                g_h2[(size_t)gr * 32 + tx * 4 + j] = acc[i][j];
        }
    }
}

// ---------------- attention dots, layer 2 (warp per node) -------------------
__global__ void k_attn2(const float* __restrict__ att_src, const float* __restrict__ att_dst, int n) {
    int warp = (blockIdx.x * blockDim.x + threadIdx.x) >> 5;
    int lane = threadIdx.x & 31;
    if (warp >= n) return;
    float v = g_h2[(size_t)warp * 32 + lane];
    float ps = v * att_src[lane];
    float pd = v * att_dst[lane];
    #pragma unroll
    for (int off = 16; off >= 1; off >>= 1) {
        ps += __shfl_xor_sync(0xffffffffu, ps, off);
        pd += __shfl_xor_sync(0xffffffffu, pd, off);
    }
    if (lane == 0) { g_as2[warp] = ps; g_ad2[warp] = pd; }
}

__global__ void k_edgeA2(const int* __restrict__ ei, int E, int etot) {
    int e = blockIdx.x * blockDim.x + threadIdx.x;
    if (e >= etot) return;
    int s, d; edge_sd(ei, e, E, s, d);
    float v = g_as2[s] + g_ad2[d];
    v = (v > 0.f) ? v : NEG_SLOPE * v;
    atomicMax(&g_emax2[d], f2u_ord(v));
}

__global__ void k_edgeB2(const int* __restrict__ ei, int E, int etot) {
    int e = blockIdx.x * blockDim.x + threadIdx.x;
    if (e >= etot) return;
    int s, d; edge_sd(ei, e, E, s, d);
    float v = g_as2[s] + g_ad2[d];
    v = (v > 0.f) ? v : NEG_SLOPE * v;
    float m  = u2f_ord(g_emax2[d]);
    float ex = __expf(v - m);
    g_eexp2[e] = ex;
    atomicAdd(&g_esum2[d], ex);
}

__global__ void k_edgeC2(const int* __restrict__ ei, int E, int etot) {
    int warp = (blockIdx.x * blockDim.x + threadIdx.x) >> 5;
    int lane = threadIdx.x & 31;
    if (warp >= etot) return;
    int s, d; edge_sd(ei, warp, E, s, d);
    float al = g_eexp2[warp] / (g_esum2[d] + 1e-16f);
    atomicAdd(&g_out2[(size_t)d * 32 + lane], g_h2[(size_t)s * 32 + lane] * al);
}

// ---------------- final: + b2, log_softmax ----------------------------------
__global__ void k_final(const float* __restrict__ b2, float* __restrict__ out, int n) {
    int warp = (blockIdx.x * blockDim.x + threadIdx.x) >> 5;
    int lane = threadIdx.x & 31;
    if (warp >= n) return;
    float v = g_out2[(size_t)warp * 32 + lane] + b2[lane];
    float m = v;
    #pragma unroll
    for (int off = 16; off >= 1; off >>= 1)
        m = fmaxf(m, __shfl_xor_sync(0xffffffffu, m, off));
    float ex = __expf(v - m);
    float sum = ex;
    #pragma unroll
    for (int off = 16; off >= 1; off >>= 1)
        sum += __shfl_xor_sync(0xffffffffu, sum, off);
    out[(size_t)warp * 32 + lane] = v - m - logf(sum);
}

// ---------------- launch -----------------------------------------------------
extern "C" void kernel_launch(void* const* d_in, const int* in_sizes, int n_in,
                              void* d_out, int out_size) {
    const float* x    = (const float*)d_in[0];
    const int*   ei   = (const int*)d_in[1];      // int64 -> int32 by harness
    const float* W1   = (const float*)d_in[2];
    const float* as1  = (const float*)d_in[3];
    const float* ad1  = (const float*)d_in[4];
    const float* b1   = (const float*)d_in[5];
    const float* W2   = (const float*)d_in[6];
    const float* as2  = (const float*)d_in[7];
    const float* ad2  = (const float*)d_in[8];
    const float* b2   = (const float*)d_in[9];
    float* out = (float*)d_out;

    int n = in_sizes[0] / FIN;           // 50000
    int E = in_sizes[1] / 2;             // 800000
    int etot = E + n;

    k_init<<<4096, 256>>>(n);

    dim3 g1(256 / G1_BN, (n + G1_BM - 1) / G1_BM);
    k_gemm1<<<g1, 256>>>(x, W1, n);

    k_attn1<<<(n + 7) / 8, 256>>>(as1, ad1, n);

    int tA = etot * 4;
    k_edgeA1<<<(tA + 255) / 256, 256>>>(ei, E, etot);
    k_edgeB1<<<(tA + 255) / 256, 256>>>(ei, E, etot);
    k_edgeC1<<<(etot + 7) / 8, 256>>>(ei, E, etot);

    dim3 g2(1, (n + G2_BM - 1) / G2_BM);
    k_gemm2<<<g2, 256>>>(b1, W2, n);

    k_attn2<<<(n + 7) / 8, 256>>>(as2, ad2, n);

    k_edgeA2<<<(etot + 255) / 256, 256>>>(ei, E, etot);
    k_edgeB2<<<(etot + 255) / 256, 256>>>(ei, E, etot);
    k_edgeC2<<<(etot + 7) / 8, 256>>>(ei, E, etot);

    k_final<<<(n + 7) / 8, 256>>>(b2, out, n);
}

// round 4
// speedup vs baseline: 1.3756x; 1.3756x over previous
#include <cuda_runtime.h>
#include <math.h>

#define NN    50000
#define EE    800000
#define FIN   256
#define HID   64
#define HEADS 4
#define CLS   32
#define ETOT  (EE + NN)
#define NEG_SLOPE 0.2f

// ---------------- scratch (device globals) ----------------------------------
__device__ float g_h1[NN * 256];      // layer-1 linear output [N,4,64]
__device__ float g_as1[NN * 4];
__device__ float g_ad1[NN * 4];
__device__ float g_agg1[NN * 256];    // layer-1 aggregated (pre-bias/relu)
__device__ float g_h2[NN * 32];       // layer-2 linear output
__device__ float g_as2[NN];
__device__ float g_ad2[NN];
// CSR (dst-bucketed incoming edges; slot stores src node id)
__device__ int   g_deg[NN];           // counts, then scatter cursor
__device__ int   g_rowstart[NN + 1];
__device__ int   g_col[ETOT];

// ---------------- CSR build --------------------------------------------------
__global__ void k_deg_init(int n) {
    int i = blockIdx.x * blockDim.x + threadIdx.x;
    if (i < n) g_deg[i] = 1;          // self-loop pre-counted
}

__global__ void k_count(const int* __restrict__ ei, int E) {
    int e = blockIdx.x * blockDim.x + threadIdx.x;
    if (e < E) atomicAdd(&g_deg[ei[E + e]], 1);
}

// single-block exclusive scan over n counters; also primes cursor = rowstart
__global__ void k_scan(int n) {
    __shared__ int sh[1024];
    int tid = threadIdx.x;
    int chunk = (n + 1023) / 1024;
    int beg = tid * chunk;
    int end = min(beg + chunk, n);
    int s = 0;
    for (int i = beg; i < end; i++) s += g_deg[i];
    sh[tid] = s;
    __syncthreads();
    #pragma unroll
    for (int off = 1; off < 1024; off <<= 1) {
        int v = (tid >= off) ? sh[tid - off] : 0;
        __syncthreads();
        sh[tid] += v;
        __syncthreads();
    }
    int run = (tid == 0) ? 0 : sh[tid - 1];
    for (int i = beg; i < end; i++) {
        int c = g_deg[i];
        g_rowstart[i] = run;
        g_deg[i] = run;              // cursor for scatter
        run += c;
    }
    if (tid == 0) g_rowstart[n] = sh[1023];
}

__global__ void k_scatter(const int* __restrict__ ei, int E, int etot) {
    int e = blockIdx.x * blockDim.x + threadIdx.x;
    if (e >= etot) return;
    int s, d;
    if (e < E) { s = ei[e]; d = ei[E + e]; }
    else       { s = d = e - E; }
    int pos = atomicAdd(&g_deg[d], 1);
    g_col[pos] = s;
}

// ---------------- GEMM1: [M,256] @ [256,256] -> g_h1 ------------------------
#define G1_BM 64
#define G1_BN 64
#define G1_BK 16
__global__ void k_gemm1(const float* __restrict__ A, const float* __restrict__ B, int M) {
    __shared__ float As[G1_BK][G1_BM + 4];
    __shared__ float Bs[G1_BK][G1_BN + 4];
    int tid = threadIdx.x;
    int tx = tid % 16, ty = tid / 16;
    int row0 = blockIdx.y * G1_BM, col0 = blockIdx.x * G1_BN;
    float acc[4][4] = {};
    for (int k0 = 0; k0 < 256; k0 += G1_BK) {
        #pragma unroll
        for (int i = 0; i < 4; i++) {
            int idx = tid + i * 256;
            int m = idx / G1_BK, k = idx % G1_BK;
            int gr = row0 + m;
            As[k][m] = (gr < M) ? A[gr * 256 + k0 + k] : 0.f;
        }
        #pragma unroll
        for (int i = 0; i < 4; i++) {
            int idx = tid + i * 256;
            int k = idx / G1_BN, nn = idx % G1_BN;
            Bs[k][nn] = B[(k0 + k) * 256 + col0 + nn];
        }
        __syncthreads();
        #pragma unroll
        for (int kk = 0; kk < G1_BK; kk++) {
            float a[4], b[4];
            #pragma unroll
            for (int i = 0; i < 4; i++) a[i] = As[kk][ty * 4 + i];
            #pragma unroll
            for (int j = 0; j < 4; j++) b[j] = Bs[kk][tx * 4 + j];
            #pragma unroll
            for (int i = 0; i < 4; i++)
                #pragma unroll
                for (int j = 0; j < 4; j++) acc[i][j] += a[i] * b[j];
        }
        __syncthreads();
    }
    #pragma unroll
    for (int i = 0; i < 4; i++) {
        int gr = row0 + ty * 4 + i;
        if (gr < M) {
            #pragma unroll
            for (int j = 0; j < 4; j++)
                g_h1[gr * 256 + col0 + tx * 4 + j] = acc[i][j];
        }
    }
}

// ---------------- attention dots, layer 1 (warp per node) -------------------
__global__ void k_attn1(const float* __restrict__ att_src, const float* __restrict__ att_dst, int n) {
    int warp = (blockIdx.x * blockDim.x + threadIdx.x) >> 5;
    int lane = threadIdx.x & 31;
    if (warp >= n) return;
    const float4* hr = (const float4*)(g_h1 + (size_t)warp * 256);
    const float4* sa = (const float4*)att_src;
    const float4* da = (const float4*)att_dst;
    float4 v0 = hr[lane], v1 = hr[lane + 32];
    float4 s0 = sa[lane], s1 = sa[lane + 32];
    float4 d0 = da[lane], d1 = da[lane + 32];
    float ps0 = v0.x*s0.x + v0.y*s0.y + v0.z*s0.z + v0.w*s0.w;
    float ps1 = v1.x*s1.x + v1.y*s1.y + v1.z*s1.z + v1.w*s1.w;
    float pd0 = v0.x*d0.x + v0.y*d0.y + v0.z*d0.z + v0.w*d0.w;
    float pd1 = v1.x*d1.x + v1.y*d1.y + v1.z*d1.z + v1.w*d1.w;
    #pragma unroll
    for (int off = 1; off < 16; off <<= 1) {
        ps0 += __shfl_xor_sync(0xffffffffu, ps0, off);
        ps1 += __shfl_xor_sync(0xffffffffu, ps1, off);
        pd0 += __shfl_xor_sync(0xffffffffu, pd0, off);
        pd1 += __shfl_xor_sync(0xffffffffu, pd1, off);
    }
    if (lane == 0)  { g_as1[warp*4+0] = ps0; g_as1[warp*4+2] = ps1;
                      g_ad1[warp*4+0] = pd0; g_ad1[warp*4+2] = pd1; }
    if (lane == 16) { g_as1[warp*4+1] = ps0; g_as1[warp*4+3] = ps1;
                      g_ad1[warp*4+1] = pd0; g_ad1[warp*4+3] = pd1; }
}

// ---------------- fused layer-1 softmax + aggregate (block per dst) ---------
__global__ void __launch_bounds__(256) k_agg1(int n) {
    int d = blockIdx.x;
    int tid = threadIdx.x;
    int h = tid >> 6;                         // head for this channel
    int beg = g_rowstart[d], end = g_rowstart[d + 1];
    float adv = g_ad1[d * 4 + h];
    // pass 1: segment max
    float mx = -3.4e38f;
    for (int i = beg; i < end; i++) {
        int s = g_col[i];
        float v = g_as1[s * 4 + h] + adv;
        v = (v > 0.f) ? v : NEG_SLOPE * v;
        mx = fmaxf(mx, v);
    }
    // pass 2: exp-sum + unnormalized aggregate
    float sum = 0.f, acc = 0.f;
    for (int i = beg; i < end; i++) {
        int s = g_col[i];
        float v = g_as1[s * 4 + h] + adv;
        v = (v > 0.f) ? v : NEG_SLOPE * v;
        float ex = __expf(v - mx);
        sum += ex;
        acc += g_h1[(size_t)s * 256 + tid] * ex;
    }
    g_agg1[(size_t)d * 256 + tid] = acc / (sum + 1e-16f);
}

// ---------------- GEMM2: relu(agg1 + b1) @ W2 -> g_h2  [M,256]@[256,32] -----
#define G2_BM 128
#define G2_BN 32
#define G2_BK 32
__global__ void k_gemm2(const float* __restrict__ b1, const float* __restrict__ W2, int M) {
    __shared__ float As[G2_BK][G2_BM + 4];
    __shared__ float Bs[G2_BK][G2_BN + 2];
    int tid = threadIdx.x;
    int tx = tid % 8, ty = tid / 8;
    int row0 = blockIdx.y * G2_BM;
    float acc[4][4] = {};
    for (int k0 = 0; k0 < 256; k0 += G2_BK) {
        #pragma unroll
        for (int i = 0; i < 16; i++) {
            int idx = tid + i * 256;
            int m = idx / G2_BK, k = idx % G2_BK;
            int gr = row0 + m;
            float v = 0.f;
            if (gr < M) {
                v = g_agg1[(size_t)gr * 256 + k0 + k] + b1[k0 + k];
                v = fmaxf(v, 0.f);
            }
            As[k][m] = v;
        }
        #pragma unroll
        for (int i = 0; i < 4; i++) {
            int idx = tid + i * 256;
            int k = idx / G2_BN, nn = idx % G2_BN;
            Bs[k][nn] = W2[(k0 + k) * 32 + nn];
        }
        __syncthreads();
        #pragma unroll
        for (int kk = 0; kk < G2_BK; kk++) {
            float a[4], b[4];
            #pragma unroll
            for (int i = 0; i < 4; i++) a[i] = As[kk][ty * 4 + i];
            #pragma unroll
            for (int j = 0; j < 4; j++) b[j] = Bs[kk][tx * 4 + j];
            #pragma unroll
            for (int i = 0; i < 4; i++)
                #pragma unroll
                for (int j = 0; j < 4; j++) acc[i][j] += a[i] * b[j];
        }
        __syncthreads();
    }
    #pragma unroll
    for (int i = 0; i < 4; i++) {
        int gr = row0 + ty * 4 + i;
        if (gr < M) {
            #pragma unroll
            for (int j = 0; j < 4; j++)
                g_h2[(size_t)gr * 32 + tx * 4 + j] = acc[i][j];
        }
    }
}

// ---------------- attention dots, layer 2 (warp per node) -------------------
__global__ void k_attn2(const float* __restrict__ att_src, const float* __restrict__ att_dst, int n) {
    int warp = (blockIdx.x * blockDim.x + threadIdx.x) >> 5;
    int lane = threadIdx.x & 31;
    if (warp >= n) return;
    float v = g_h2[(size_t)warp * 32 + lane];
    float ps = v * att_src[lane];
    float pd = v * att_dst[lane];
    #pragma unroll
    for (int off = 16; off >= 1; off >>= 1) {
        ps += __shfl_xor_sync(0xffffffffu, ps, off);
        pd += __shfl_xor_sync(0xffffffffu, pd, off);
    }
    if (lane == 0) { g_as2[warp] = ps; g_ad2[warp] = pd; }
}

// ----- fused layer-2 softmax + aggregate + bias + log_softmax (warp/dst) ----
__global__ void __launch_bounds__(256) k_agg2(const float* __restrict__ b2,
                                              float* __restrict__ out, int n) {
    int d = (blockIdx.x * blockDim.x + threadIdx.x) >> 5;
    int lane = threadIdx.x & 31;
    if (d >= n) return;
    int beg = g_rowstart[d], end = g_rowstart[d + 1];
    float adv = g_ad2[d];
    float mx = -3.4e38f;
    for (int i = beg; i < end; i++) {
        float v = g_as2[g_col[i]] + adv;
        v = (v > 0.f) ? v : NEG_SLOPE * v;
        mx = fmaxf(mx, v);
    }
    float sum = 0.f, acc = 0.f;
    for (int i = beg; i < end; i++) {
        int s = g_col[i];
        float v = g_as2[s] + adv;
        v = (v > 0.f) ? v : NEG_SLOPE * v;
        float ex = __expf(v - mx);
        sum += ex;
        acc += g_h2[(size_t)s * 32 + lane] * ex;
    }
    float val = acc / (sum + 1e-16f) + b2[lane];
    // log-softmax across 32 classes (one warp)
    float m2 = val;
    #pragma unroll
    for (int off = 16; off >= 1; off >>= 1)
        m2 = fmaxf(m2, __shfl_xor_sync(0xffffffffu, m2, off));
    float ex = __expf(val - m2);
    float s2 = ex;
    #pragma unroll
    for (int off = 16; off >= 1; off >>= 1)
        s2 += __shfl_xor_sync(0xffffffffu, s2, off);
    out[(size_t)d * 32 + lane] = val - m2 - logf(s2);
}

// ---------------- launch -----------------------------------------------------
extern "C" void kernel_launch(void* const* d_in, const int* in_sizes, int n_in,
                              void* d_out, int out_size) {
    const float* x    = (const float*)d_in[0];
    const int*   ei   = (const int*)d_in[1];
    const float* W1   = (const float*)d_in[2];
    const float* as1  = (const float*)d_in[3];
    const float* ad1  = (const float*)d_in[4];
    const float* b1   = (const float*)d_in[5];
    const float* W2   = (const float*)d_in[6];
    const float* as2  = (const float*)d_in[7];
    const float* ad2  = (const float*)d_in[8];
    const float* b2   = (const float*)d_in[9];
    float* out = (float*)d_out;

    int n = in_sizes[0] / FIN;
    int E = in_sizes[1] / 2;
    int etot = E + n;

    // CSR build (runs concurrently-safe as sequential launches in one stream)
    k_deg_init<<<(n + 255) / 256, 256>>>(n);
    k_count<<<(E + 255) / 256, 256>>>(ei, E);
    k_scan<<<1, 1024>>>(n);
    k_scatter<<<(etot + 255) / 256, 256>>>(ei, E, etot);

    dim3 g1(256 / G1_BN, (n + G1_BM - 1) / G1_BM);
    k_gemm1<<<g1, 256>>>(x, W1, n);

    k_attn1<<<(n + 7) / 8, 256>>>(as1, ad1, n);

    k_agg1<<<n, 256>>>(n);

    dim3 g2(1, (n + G2_BM - 1) / G2_BM);
    k_gemm2<<<g2, 256>>>(b1, W2, n);

    k_attn2<<<(n + 7) / 8, 256>>>(as2, ad2, n);

    k_agg2<<<(n * 32 + 255) / 256, 256>>>(b2, out, n);
}

// round 5
// speedup vs baseline: 1.8033x; 1.3109x over previous
#include <cuda_runtime.h>
#include <math.h>

#define NN    50000
#define EE    800000
#define FIN   256
#define ETOT  (EE + NN)
#define NEG_SLOPE 0.2f

// ---------------- scratch (device globals) ----------------------------------
__device__ float g_h1[NN * 256];      // layer-1 linear output [N,4,64]
__device__ float g_as1[NN * 4];
__device__ float g_ad1[NN * 4];
__device__ float g_agg1[NN * 256];    // layer-1 aggregated, relu(x+b1) applied
__device__ float g_h2[NN * 32];       // layer-2 linear output
__device__ float g_as2[NN];
__device__ float g_ad2[NN];
__device__ float g_alpha1[ETOT * 4];  // unnormalized exp weight per CSR slot, head
__device__ float g_rsum1[NN * 4];     // 1/(sum+eps) per (dst, head)
__device__ float g_alpha2[ETOT];
__device__ float g_rsum2[NN];
// CSR (dst-bucketed incoming edges; slot stores src node id)
__device__ int   g_deg[NN];           // counts, then scatter cursor
__device__ int   g_rowstart[NN + 1];
__device__ int   g_col[ETOT];

// ---------------- CSR build --------------------------------------------------
__global__ void k_deg_init(int n) {
    int i = blockIdx.x * blockDim.x + threadIdx.x;
    if (i < n) g_deg[i] = 1;          // self-loop pre-counted
}

__global__ void k_count(const int* __restrict__ ei, int E) {
    int e = blockIdx.x * blockDim.x + threadIdx.x;
    if (e < E) atomicAdd(&g_deg[ei[E + e]], 1);
}

__global__ void k_scan(int n) {
    __shared__ int sh[1024];
    int tid = threadIdx.x;
    int chunk = (n + 1023) / 1024;
    int beg = tid * chunk;
    int end = min(beg + chunk, n);
    int s = 0;
    for (int i = beg; i < end; i++) s += g_deg[i];
    sh[tid] = s;
    __syncthreads();
    #pragma unroll
    for (int off = 1; off < 1024; off <<= 1) {
        int v = (tid >= off) ? sh[tid - off] : 0;
        __syncthreads();
        sh[tid] += v;
        __syncthreads();
    }
    int run = (tid == 0) ? 0 : sh[tid - 1];
    for (int i = beg; i < end; i++) {
        int c = g_deg[i];
        g_rowstart[i] = run;
        g_deg[i] = run;              // cursor for scatter
        run += c;
    }
    if (tid == 0) g_rowstart[n] = sh[1023];
}

__global__ void k_scatter(const int* __restrict__ ei, int E, int etot) {
    int e = blockIdx.x * blockDim.x + threadIdx.x;
    if (e >= etot) return;
    int s, d;
    if (e < E) { s = ei[e]; d = ei[E + e]; }
    else       { s = d = e - E; }
    int pos = atomicAdd(&g_deg[d], 1);
    g_col[pos] = s;
}

// ---------------- GEMM1: [M,256] @ [256,256] -> g_h1 ------------------------
#define T1_BM 128
#define T1_BN 128
#define T1_BK 16
__global__ void __launch_bounds__(256) k_gemm1(const float* __restrict__ A,
                                               const float* __restrict__ B, int M) {
    __shared__ float As[T1_BK][T1_BM + 4];
    __shared__ float Bs[T1_BK][T1_BN + 4];
    int tid = threadIdx.x;
    int row0 = blockIdx.y * T1_BM, col0 = blockIdx.x * T1_BN;
    int tx = tid % 16, ty = tid / 16;
    float acc[8][8] = {};
    for (int k0 = 0; k0 < 256; k0 += T1_BK) {
        // A tile: 128 rows x 16 cols = 512 float4
        #pragma unroll
        for (int i = 0; i < 2; i++) {
            int slot = tid + i * 256;
            int r = slot >> 2, kq = slot & 3;
            int gr = row0 + r;
            float4 v = make_float4(0.f, 0.f, 0.f, 0.f);
            if (gr < M) v = *(const float4*)(A + (size_t)gr * 256 + k0 + kq * 4);
            As[kq * 4 + 0][r] = v.x;
            As[kq * 4 + 1][r] = v.y;
            As[kq * 4 + 2][r] = v.z;
            As[kq * 4 + 3][r] = v.w;
        }
        // B tile: 16 rows x 128 cols = 512 float4
        #pragma unroll
        for (int i = 0; i < 2; i++) {
            int slot = tid + i * 256;
            int r = slot >> 5, cq = slot & 31;
            float4 v = *(const float4*)(B + (size_t)(k0 + r) * 256 + col0 + cq * 4);
            *(float4*)&Bs[r][cq * 4] = v;
        }
        __syncthreads();
        #pragma unroll
        for (int kk = 0; kk < T1_BK; kk++) {
            float a[8], b[8];
            *(float4*)(a)     = *(float4*)&As[kk][ty * 8];
            *(float4*)(a + 4) = *(float4*)&As[kk][ty * 8 + 4];
            *(float4*)(b)     = *(float4*)&Bs[kk][tx * 8];
            *(float4*)(b + 4) = *(float4*)&Bs[kk][tx * 8 + 4];
            #pragma unroll
            for (int i = 0; i < 8; i++)
                #pragma unroll
                for (int j = 0; j < 8; j++) acc[i][j] += a[i] * b[j];
        }
        __syncthreads();
    }
    #pragma unroll
    for (int i = 0; i < 8; i++) {
        int gr = row0 + ty * 8 + i;
        if (gr < M) {
            float* op = g_h1 + (size_t)gr * 256 + col0 + tx * 8;
            *(float4*)(op)     = *(float4*)&acc[i][0];
            *(float4*)(op + 4) = *(float4*)&acc[i][4];
        }
    }
}

// ---------------- attention dots, layer 1 (warp per node) -------------------
__global__ void k_attn1(const float* __restrict__ att_src, const float* __restrict__ att_dst, int n) {
    int warp = (blockIdx.x * blockDim.x + threadIdx.x) >> 5;
    int lane = threadIdx.x & 31;
    if (warp >= n) return;
    const float4* hr = (const float4*)(g_h1 + (size_t)warp * 256);
    const float4* sa = (const float4*)att_src;
    const float4* da = (const float4*)att_dst;
    float4 v0 = hr[lane], v1 = hr[lane + 32];
    float4 s0 = sa[lane], s1 = sa[lane + 32];
    float4 d0 = da[lane], d1 = da[lane + 32];
    float ps0 = v0.x*s0.x + v0.y*s0.y + v0.z*s0.z + v0.w*s0.w;
    float ps1 = v1.x*s1.x + v1.y*s1.y + v1.z*s1.z + v1.w*s1.w;
    float pd0 = v0.x*d0.x + v0.y*d0.y + v0.z*d0.z + v0.w*d0.w;
    float pd1 = v1.x*d1.x + v1.y*d1.y + v1.z*d1.z + v1.w*d1.w;
    #pragma unroll
    for (int off = 1; off < 16; off <<= 1) {
        ps0 += __shfl_xor_sync(0xffffffffu, ps0, off);
        ps1 += __shfl_xor_sync(0xffffffffu, ps1, off);
        pd0 += __shfl_xor_sync(0xffffffffu, pd0, off);
        pd1 += __shfl_xor_sync(0xffffffffu, pd1, off);
    }
    if (lane == 0)  { g_as1[warp*4+0] = ps0; g_as1[warp*4+2] = ps1;
                      g_ad1[warp*4+0] = pd0; g_ad1[warp*4+2] = pd1; }
    if (lane == 16) { g_as1[warp*4+1] = ps0; g_as1[warp*4+3] = ps1;
                      g_ad1[warp*4+1] = pd0; g_ad1[warp*4+3] = pd1; }
}

// ---------------- alpha precompute, layer 1 (thread per dst,head) -----------
__global__ void k_alpha1(int n) {
    int idx = blockIdx.x * blockDim.x + threadIdx.x;
    if (idx >= n * 4) return;
    int d = idx >> 2, h = idx & 3;
    int beg = g_rowstart[d], end = g_rowstart[d + 1];
    float adv = g_ad1[d * 4 + h];
    float mx = -3.4e38f;
    for (int i = beg; i < end; i++) {
        float v = g_as1[g_col[i] * 4 + h] + adv;
        v = (v > 0.f) ? v : NEG_SLOPE * v;
        mx = fmaxf(mx, v);
    }
    float sum = 0.f;
    for (int i = beg; i < end; i++) {
        float v = g_as1[g_col[i] * 4 + h] + adv;
        v = (v > 0.f) ? v : NEG_SLOPE * v;
        float ex = __expf(v - mx);
        g_alpha1[i * 4 + h] = ex;
        sum += ex;
    }
    g_rsum1[d * 4 + h] = 1.f / (sum + 1e-16f);
}

// ------- fused layer-1 aggregate + bias + relu (block per dst, 1 pass) ------
__global__ void __launch_bounds__(256) k_agg1(const float* __restrict__ b1) {
    int d = blockIdx.x;
    int tid = threadIdx.x;
    int h = tid >> 6;
    int beg = g_rowstart[d], end = g_rowstart[d + 1];
    float acc = 0.f;
    for (int i = beg; i < end; i++) {
        int s = g_col[i];
        float w = g_alpha1[i * 4 + h];
        acc += g_h1[(size_t)s * 256 + tid] * w;
    }
    float val = acc * g_rsum1[d * 4 + h] + b1[tid];
    g_agg1[(size_t)d * 256 + tid] = fmaxf(val, 0.f);
}

// ---------------- GEMM2: g_agg1 @ W2 -> g_h2  [M,256]@[256,32] --------------
#define G2_BM 128
#define G2_BN 32
#define G2_BK 32
__global__ void k_gemm2(const float* __restrict__ W2, int M) {
    __shared__ float As[G2_BK][G2_BM + 4];
    __shared__ float Bs[G2_BK][G2_BN + 2];
    int tid = threadIdx.x;
    int tx = tid % 8, ty = tid / 8;
    int row0 = blockIdx.y * G2_BM;
    float acc[4][4] = {};
    for (int k0 = 0; k0 < 256; k0 += G2_BK) {
        #pragma unroll
        for (int i = 0; i < 16; i++) {
            int idx = tid + i * 256;
            int m = idx / G2_BK, k = idx % G2_BK;
            int gr = row0 + m;
            As[k][m] = (gr < M) ? g_agg1[(size_t)gr * 256 + k0 + k] : 0.f;
        }
        #pragma unroll
        for (int i = 0; i < 4; i++) {
            int idx = tid + i * 256;
            int k = idx / G2_BN, nn = idx % G2_BN;
            Bs[k][nn] = W2[(k0 + k) * 32 + nn];
        }
        __syncthreads();
        #pragma unroll
        for (int kk = 0; kk < G2_BK; kk++) {
            float a[4], b[4];
            #pragma unroll
            for (int i = 0; i < 4; i++) a[i] = As[kk][ty * 4 + i];
            #pragma unroll
            for (int j = 0; j < 4; j++) b[j] = Bs[kk][tx * 4 + j];
            #pragma unroll
            for (int i = 0; i < 4; i++)
                #pragma unroll
                for (int j = 0; j < 4; j++) acc[i][j] += a[i] * b[j];
        }
        __syncthreads();
    }
    #pragma unroll
    for (int i = 0; i < 4; i++) {
        int gr = row0 + ty * 4 + i;
        if (gr < M) {
            #pragma unroll
            for (int j = 0; j < 4; j++)
                g_h2[(size_t)gr * 32 + tx * 4 + j] = acc[i][j];
        }
    }
}

// ---------------- attention dots, layer 2 (warp per node) -------------------
__global__ void k_attn2(const float* __restrict__ att_src, const float* __restrict__ att_dst, int n) {
    int warp = (blockIdx.x * blockDim.x + threadIdx.x) >> 5;
    int lane = threadIdx.x & 31;
    if (warp >= n) return;
    float v = g_h2[(size_t)warp * 32 + lane];
    float ps = v * att_src[lane];
    float pd = v * att_dst[lane];
    #pragma unroll
    for (int off = 16; off >= 1; off >>= 1) {
        ps += __shfl_xor_sync(0xffffffffu, ps, off);
        pd += __shfl_xor_sync(0xffffffffu, pd, off);
    }
    if (lane == 0) { g_as2[warp] = ps; g_ad2[warp] = pd; }
}

// ---------------- alpha precompute, layer 2 (thread per dst) ----------------
__global__ void k_alpha2(int n) {
    int d = blockIdx.x * blockDim.x + threadIdx.x;
    if (d >= n) return;
    int beg = g_rowstart[d], end = g_rowstart[d + 1];
    float adv = g_ad2[d];
    float mx = -3.4e38f;
    for (int i = beg; i < end; i++) {
        float v = g_as2[g_col[i]] + adv;
        v = (v > 0.f) ? v : NEG_SLOPE * v;
        mx = fmaxf(mx, v);
    }
    float sum = 0.f;
    for (int i = beg; i < end; i++) {
        float v = g_as2[g_col[i]] + adv;
        v = (v > 0.f) ? v : NEG_SLOPE * v;
        float ex = __expf(v - mx);
        g_alpha2[i] = ex;
        sum += ex;
    }
    g_rsum2[d] = 1.f / (sum + 1e-16f);
}

// ----- fused layer-2 aggregate + bias + log_softmax (warp per dst) ----------
__global__ void __launch_bounds__(256) k_agg2(const float* __restrict__ b2,
                                              float* __restrict__ out, int n) {
    int d = (blockIdx.x * blockDim.x + threadIdx.x) >> 5;
    int lane = threadIdx.x & 31;
    if (d >= n) return;
    int beg = g_rowstart[d], end = g_rowstart[d + 1];
    float acc = 0.f;
    for (int i = beg; i < end; i++) {
        int s = g_col[i];
        acc += g_h2[(size_t)s * 32 + lane] * g_alpha2[i];
    }
    float val = acc * g_rsum2[d] + b2[lane];
    float m2 = val;
    #pragma unroll
    for (int off = 16; off >= 1; off >>= 1)
        m2 = fmaxf(m2, __shfl_xor_sync(0xffffffffu, m2, off));
    float ex = __expf(val - m2);
    float s2 = ex;
    #pragma unroll
    for (int off = 16; off >= 1; off >>= 1)
        s2 += __shfl_xor_sync(0xffffffffu, s2, off);
    out[(size_t)d * 32 + lane] = val - m2 - logf(s2);
}

// ---------------- launch -----------------------------------------------------
extern "C" void kernel_launch(void* const* d_in, const int* in_sizes, int n_in,
                              void* d_out, int out_size) {
    const float* x    = (const float*)d_in[0];
    const int*   ei   = (const int*)d_in[1];
    const float* W1   = (const float*)d_in[2];
    const float* as1  = (const float*)d_in[3];
    const float* ad1  = (const float*)d_in[4];
    const float* b1   = (const float*)d_in[5];
    const float* W2   = (const float*)d_in[6];
    const float* as2  = (const float*)d_in[7];
    const float* ad2  = (const float*)d_in[8];
    const float* b2   = (const float*)d_in[9];
    float* out = (float*)d_out;

    int n = in_sizes[0] / FIN;
    int E = in_sizes[1] / 2;
    int etot = E + n;

    k_deg_init<<<(n + 255) / 256, 256>>>(n);
    k_count<<<(E + 255) / 256, 256>>>(ei, E);
    k_scan<<<1, 1024>>>(n);
    k_scatter<<<(etot + 255) / 256, 256>>>(ei, E, etot);

    dim3 g1(256 / T1_BN, (n + T1_BM - 1) / T1_BM);
    k_gemm1<<<g1, 256>>>(x, W1, n);

    k_attn1<<<(n + 7) / 8, 256>>>(as1, ad1, n);
    k_alpha1<<<(n * 4 + 255) / 256, 256>>>(n);
    k_agg1<<<n, 256>>>(b1);

    dim3 g2(1, (n + G2_BM - 1) / G2_BM);
    k_gemm2<<<g2, 256>>>(W2, n);

    k_attn2<<<(n + 7) / 8, 256>>>(as2, ad2, n);
    k_alpha2<<<(n + 255) / 256, 256>>>(n);
    k_agg2<<<(n * 32 + 255) / 256, 256>>>(b2, out, n);
}

// round 8
// speedup vs baseline: 2.0282x; 1.1247x over previous
#include <cuda_runtime.h>
#include <cuda_bf16.h>
#include <math.h>
#include <stdint.h>

#define NN    50000
#define EE    800000
#define FIN   256
#define ETOT  (EE + NN)
#define NEG_SLOPE 0.2f

// ---------------- scratch (device globals) ----------------------------------
__device__ float g_h1[NN * 256];      // layer-1 linear output [N,4,64]
__device__ float g_as1[NN * 4];
__device__ float g_ad1[NN * 4];
__device__ float g_agg1[NN * 256];    // layer-1 aggregated, relu(x+b1) applied
__device__ float g_h2[NN * 32];       // layer-2 linear output
__device__ float g_as2[NN];
__device__ float g_ad2[NN];
__device__ float g_alpha1[ETOT * 4];  // unnormalized exp weight per CSR slot, head
__device__ float g_rsum1[NN * 4];     // 1/(sum+eps) per (dst, head)
__device__ float g_alpha2[ETOT];
__device__ float g_rsum2[NN];
// split-bf16 operands for tensor-core GEMM1
__device__ __nv_bfloat16 g_xhi[NN * 256];
__device__ __nv_bfloat16 g_xlo[NN * 256];
__device__ __nv_bfloat16 g_w1hi[256 * 256];   // [n][k] (transposed W1)
__device__ __nv_bfloat16 g_w1lo[256 * 256];
// CSR (dst-bucketed incoming edges; slot stores src node id)
__device__ int   g_deg[NN];
__device__ int   g_rowstart[NN + 1];
__device__ int   g_col[ETOT];

// ---------------- CSR build --------------------------------------------------
__global__ void k_deg_init(int n) {
    int i = blockIdx.x * blockDim.x + threadIdx.x;
    if (i < n) g_deg[i] = 1;
}
__global__ void k_count(const int* __restrict__ ei, int E) {
    int e = blockIdx.x * blockDim.x + threadIdx.x;
    if (e < E) atomicAdd(&g_deg[ei[E + e]], 1);
}
__global__ void k_scan(int n) {
    __shared__ int sh[1024];
    int tid = threadIdx.x;
    int chunk = (n + 1023) / 1024;
    int beg = tid * chunk;
    int end = min(beg + chunk, n);
    int s = 0;
    for (int i = beg; i < end; i++) s += g_deg[i];
    sh[tid] = s;
    __syncthreads();
    #pragma unroll
    for (int off = 1; off < 1024; off <<= 1) {
        int v = (tid >= off) ? sh[tid - off] : 0;
        __syncthreads();
        sh[tid] += v;
        __syncthreads();
    }
    int run = (tid == 0) ? 0 : sh[tid - 1];
    for (int i = beg; i < end; i++) {
        int c = g_deg[i];
        g_rowstart[i] = run;
        g_deg[i] = run;
        run += c;
    }
    if (tid == 0) g_rowstart[n] = sh[1023];
}
__global__ void k_scatter(const int* __restrict__ ei, int E, int etot) {
    int e = blockIdx.x * blockDim.x + threadIdx.x;
    if (e >= etot) return;
    int s, d;
    if (e < E) { s = ei[e]; d = ei[E + e]; }
    else       { s = d = e - E; }
    int pos = atomicAdd(&g_deg[d], 1);
    g_col[pos] = s;
}

// ---------------- split-bf16 prep -------------------------------------------
__global__ void k_prep_x(const float* __restrict__ x, int total) {
    int i = blockIdx.x * blockDim.x + threadIdx.x;
    if (i >= total) return;
    float f = x[i];
    __nv_bfloat16 hi = __float2bfloat16_rn(f);
    g_xhi[i] = hi;
    g_xlo[i] = __float2bfloat16_rn(f - __bfloat162float(hi));
}
__global__ void k_prep_w(const float* __restrict__ W1) {
    int i = blockIdx.x * blockDim.x + threadIdx.x;
    if (i >= 256 * 256) return;
    int n = i >> 8, k = i & 255;
    float f = W1[k * 256 + n];
    __nv_bfloat16 hi = __float2bfloat16_rn(f);
    g_w1hi[i] = hi;
    g_w1lo[i] = __float2bfloat16_rn(f - __bfloat162float(hi));
}

// ---------------- GEMM1 via mma.sync bf16 (split hi/lo) ---------------------
// CTA tile 128x128, K chunks of 32; 8 warps (4 M x 2 N), warp tile 32x64.
#define PAD_K 40          // 32 + 8 bf16 padding -> 80-byte rows (16B aligned)
__device__ __forceinline__ void mma16816(float* c, const uint32_t* a, const uint32_t* b) {
    asm volatile(
        "mma.sync.aligned.m16n8k16.row.col.f32.bf16.bf16.f32 "
        "{%0,%1,%2,%3}, {%4,%5,%6,%7}, {%8,%9}, {%0,%1,%2,%3};"
        : "+f"(c[0]), "+f"(c[1]), "+f"(c[2]), "+f"(c[3])
        : "r"(a[0]), "r"(a[1]), "r"(a[2]), "r"(a[3]), "r"(b[0]), "r"(b[1]));
}

__global__ void __launch_bounds__(256) k_gemm1_mma(int M) {
    __shared__ __nv_bfloat16 sAhi[128 * PAD_K];
    __shared__ __nv_bfloat16 sAlo[128 * PAD_K];
    __shared__ __nv_bfloat16 sBhi[128 * PAD_K];
    __shared__ __nv_bfloat16 sBlo[128 * PAD_K];

    int tid = threadIdx.x;
    int wid = tid >> 5, lane = tid & 31;
    int wm = wid >> 1, wn = wid & 1;          // 4 x 2 warps
    int row0 = blockIdx.y * 128;
    int col0 = blockIdx.x * 128;

    float acc[2][8][4] = {};

    int lq = lane & 3;                        // lane % 4
    int lr = lane >> 2;                       // lane / 4

    for (int kc = 0; kc < 256; kc += 32) {
        // fill A tiles: 128 rows x 32 k = 512 uint4 per array, 2 per thread
        #pragma unroll
        for (int i = 0; i < 2; i++) {
            int slot = tid + i * 256;         // 0..511
            int r = slot >> 2, q = slot & 3;  // row, 16B-quad within 64B
            int gr = row0 + r;
            uint4 vh = make_uint4(0, 0, 0, 0), vl = make_uint4(0, 0, 0, 0);
            if (gr < M) {
                vh = *(const uint4*)(g_xhi + (size_t)gr * 256 + kc + q * 8);
                vl = *(const uint4*)(g_xlo + (size_t)gr * 256 + kc + q * 8);
            }
            *(uint4*)(sAhi + r * PAD_K + q * 8) = vh;
            *(uint4*)(sAlo + r * PAD_K + q * 8) = vl;
        }
        // fill B tiles: 128 n-rows x 32 k
        #pragma unroll
        for (int i = 0; i < 2; i++) {
            int slot = tid + i * 256;
            int r = slot >> 2, q = slot & 3;
            int gn = col0 + r;
            *(uint4*)(sBhi + r * PAD_K + q * 8) = *(const uint4*)(g_w1hi + (size_t)gn * 256 + kc + q * 8);
            *(uint4*)(sBlo + r * PAD_K + q * 8) = *(const uint4*)(g_w1lo + (size_t)gn * 256 + kc + q * 8);
        }
        __syncthreads();

        #pragma unroll
        for (int ks = 0; ks < 2; ks++) {
            int kb = ks * 16;
            uint32_t ahi[2][4], alo[2][4], bhi[8][2], blo[8][2];
            #pragma unroll
            for (int mt = 0; mt < 2; mt++) {
                int rbase = wm * 32 + mt * 16;
                const __nv_bfloat16* p0h = sAhi + (rbase + lr) * PAD_K + kb + lq * 2;
                const __nv_bfloat16* p1h = sAhi + (rbase + 8 + lr) * PAD_K + kb + lq * 2;
                const __nv_bfloat16* p0l = sAlo + (rbase + lr) * PAD_K + kb + lq * 2;
                const __nv_bfloat16* p1l = sAlo + (rbase + 8 + lr) * PAD_K + kb + lq * 2;
                ahi[mt][0] = *(const uint32_t*)p0h;
                ahi[mt][1] = *(const uint32_t*)p1h;
                ahi[mt][2] = *(const uint32_t*)(p0h + 8);
                ahi[mt][3] = *(const uint32_t*)(p1h + 8);
                alo[mt][0] = *(const uint32_t*)p0l;
                alo[mt][1] = *(const uint32_t*)p1l;
                alo[mt][2] = *(const uint32_t*)(p0l + 8);
                alo[mt][3] = *(const uint32_t*)(p1l + 8);
            }
            #pragma unroll
            for (int nt = 0; nt < 8; nt++) {
                int nbase = wn * 64 + nt * 8;
                const __nv_bfloat16* ph = sBhi + (nbase + lr) * PAD_K + kb + lq * 2;
                const __nv_bfloat16* pl = sBlo + (nbase + lr) * PAD_K + kb + lq * 2;
                bhi[nt][0] = *(const uint32_t*)ph;
                bhi[nt][1] = *(const uint32_t*)(ph + 8);
                blo[nt][0] = *(const uint32_t*)pl;
                blo[nt][1] = *(const uint32_t*)(pl + 8);
            }
            #pragma unroll
            for (int mt = 0; mt < 2; mt++)
                #pragma unroll
                for (int nt = 0; nt < 8; nt++) {
                    mma16816(acc[mt][nt], ahi[mt], bhi[nt]);
                    mma16816(acc[mt][nt], ahi[mt], blo[nt]);
                    mma16816(acc[mt][nt], alo[mt], bhi[nt]);
                }
        }
        __syncthreads();
    }

    // epilogue: c0,c1 at (row lr, col lq*2), c2,c3 at (row lr+8)
    #pragma unroll
    for (int mt = 0; mt < 2; mt++) {
        int r0 = row0 + wm * 32 + mt * 16 + lr;
        #pragma unroll
        for (int nt = 0; nt < 8; nt++) {
            int c = col0 + wn * 64 + nt * 8 + lq * 2;
            if (r0 < M)
                *(float2*)(g_h1 + (size_t)r0 * 256 + c) = make_float2(acc[mt][nt][0], acc[mt][nt][1]);
            if (r0 + 8 < M)
                *(float2*)(g_h1 + (size_t)(r0 + 8) * 256 + c) = make_float2(acc[mt][nt][2], acc[mt][nt][3]);
        }
    }
}

// ---------------- attention dots, layer 1 (warp per node) -------------------
__global__ void k_attn1(const float* __restrict__ att_src, const float* __restrict__ att_dst, int n) {
    int warp = (blockIdx.x * blockDim.x + threadIdx.x) >> 5;
    int lane = threadIdx.x & 31;
    if (warp >= n) return;
    const float4* hr = (const float4*)(g_h1 + (size_t)warp * 256);
    const float4* sa = (const float4*)att_src;
    const float4* da = (const float4*)att_dst;
    float4 v0 = hr[lane], v1 = hr[lane + 32];
    float4 s0 = sa[lane], s1 = sa[lane + 32];
    float4 d0 = da[lane], d1 = da[lane + 32];
    float ps0 = v0.x*s0.x + v0.y*s0.y + v0.z*s0.z + v0.w*s0.w;
    float ps1 = v1.x*s1.x + v1.y*s1.y + v1.z*s1.z + v1.w*s1.w;
    float pd0 = v0.x*d0.x + v0.y*d0.y + v0.z*d0.z + v0.w*d0.w;
    float pd1 = v1.x*d1.x + v1.y*d1.y + v1.z*d1.z + v1.w*d1.w;
    #pragma unroll
    for (int off = 1; off < 16; off <<= 1) {
        ps0 += __shfl_xor_sync(0xffffffffu, ps0, off);
        ps1 += __shfl_xor_sync(0xffffffffu, ps1, off);
        pd0 += __shfl_xor_sync(0xffffffffu, pd0, off);
        pd1 += __shfl_xor_sync(0xffffffffu, pd1, off);
    }
    if (lane == 0)  { g_as1[warp*4+0] = ps0; g_as1[warp*4+2] = ps1;
                      g_ad1[warp*4+0] = pd0; g_ad1[warp*4+2] = pd1; }
    if (lane == 16) { g_as1[warp*4+1] = ps0; g_as1[warp*4+3] = ps1;
                      g_ad1[warp*4+1] = pd0; g_ad1[warp*4+3] = pd1; }
}

// ---------------- alpha precompute, layer 1 (thread per dst,head) -----------
__global__ void k_alpha1(int n) {
    int idx = blockIdx.x * blockDim.x + threadIdx.x;
    if (idx >= n * 4) return;
    int d = idx >> 2, h = idx & 3;
    int beg = g_rowstart[d], end = g_rowstart[d + 1];
    float adv = g_ad1[d * 4 + h];
    float mx = -3.4e38f;
    for (int i = beg; i < end; i++) {
        float v = g_as1[g_col[i] * 4 + h] + adv;
        v = (v > 0.f) ? v : NEG_SLOPE * v;
        mx = fmaxf(mx, v);
    }
    float sum = 0.f;
    for (int i = beg; i < end; i++) {
        float v = g_as1[g_col[i] * 4 + h] + adv;
        v = (v > 0.f) ? v : NEG_SLOPE * v;
        float ex = __expf(v - mx);
        g_alpha1[i * 4 + h] = ex;
        sum += ex;
    }
    g_rsum1[d * 4 + h] = 1.f / (sum + 1e-16f);
}

// ------- fused layer-1 aggregate + bias + relu (block per dst, 1 pass) ------
__global__ void __launch_bounds__(256) k_agg1(const float* __restrict__ b1) {
    int d = blockIdx.x;
    int tid = threadIdx.x;
    int h = tid >> 6;
    int beg = g_rowstart[d], end = g_rowstart[d + 1];
    float acc = 0.f;
    for (int i = beg; i < end; i++) {
        int s = g_col[i];
        float w = g_alpha1[i * 4 + h];
        acc += g_h1[(size_t)s * 256 + tid] * w;
    }
    float val = acc * g_rsum1[d * 4 + h] + b1[tid];
    g_agg1[(size_t)d * 256 + tid] = fmaxf(val, 0.f);
}

// ---------------- GEMM2: g_agg1 @ W2 -> g_h2  [M,256]@[256,32] --------------
#define G2_BM 128
#define G2_BN 32
#define G2_BK 32
__global__ void k_gemm2(const float* __restrict__ W2, int M) {
    __shared__ float As[G2_BK][G2_BM + 4];
    __shared__ float Bs[G2_BK][G2_BN + 2];
    int tid = threadIdx.x;
    int tx = tid % 8, ty = tid / 8;
    int row0 = blockIdx.y * G2_BM;
    float acc[4][4] = {};
    for (int k0 = 0; k0 < 256; k0 += G2_BK) {
        #pragma unroll
        for (int i = 0; i < 16; i++) {
            int idx = tid + i * 256;
            int m = idx / G2_BK, k = idx % G2_BK;
            int gr = row0 + m;
            As[k][m] = (gr < M) ? g_agg1[(size_t)gr * 256 + k0 + k] : 0.f;
        }
        #pragma unroll
        for (int i = 0; i < 4; i++) {
            int idx = tid + i * 256;
            int k = idx / G2_BN, nn = idx % G2_BN;
            Bs[k][nn] = W2[(k0 + k) * 32 + nn];
        }
        __syncthreads();
        #pragma unroll
        for (int kk = 0; kk < G2_BK; kk++) {
            float a[4], b[4];
            #pragma unroll
            for (int i = 0; i < 4; i++) a[i] = As[kk][ty * 4 + i];
            #pragma unroll
            for (int j = 0; j < 4; j++) b[j] = Bs[kk][tx * 4 + j];
            #pragma unroll
            for (int i = 0; i < 4; i++)
                #pragma unroll
                for (int j = 0; j < 4; j++) acc[i][j] += a[i] * b[j];
        }
        __syncthreads();
    }
    #pragma unroll
    for (int i = 0; i < 4; i++) {
        int gr = row0 + ty * 4 + i;
        if (gr < M) {
            #pragma unroll
            for (int j = 0; j < 4; j++)
                g_h2[(size_t)gr * 32 + tx * 4 + j] = acc[i][j];
        }
    }
}

// ---------------- attention dots, layer 2 (warp per node) -------------------
__global__ void k_attn2(const float* __restrict__ att_src, const float* __restrict__ att_dst, int n) {
    int warp = (blockIdx.x * blockDim.x + threadIdx.x) >> 5;
    int lane = threadIdx.x & 31;
    if (warp >= n) return;
    float v = g_h2[(size_t)warp * 32 + lane];
    float ps = v * att_src[lane];
    float pd = v * att_dst[lane];
    #pragma unroll
    for (int off = 16; off >= 1; off >>= 1) {
        ps += __shfl_xor_sync(0xffffffffu, ps, off);
        pd += __shfl_xor_sync(0xffffffffu, pd, off);
    }
    if (lane == 0) { g_as2[warp] = ps; g_ad2[warp] = pd; }
}

// ---------------- alpha precompute, layer 2 (thread per dst) ----------------
__global__ void k_alpha2(int n) {
    int d = blockIdx.x * blockDim.x + threadIdx.x;
    if (d >= n) return;
    int beg = g_rowstart[d], end = g_rowstart[d + 1];
    float adv = g_ad2[d];
    float mx = -3.4e38f;
    for (int i = beg; i < end; i++) {
        float v = g_as2[g_col[i]] + adv;
        v = (v > 0.f) ? v : NEG_SLOPE * v;
        mx = fmaxf(mx, v);
    }
    float sum = 0.f;
    for (int i = beg; i < end; i++) {
        float v = g_as2[g_col[i]] + adv;
        v = (v > 0.f) ? v : NEG_SLOPE * v;
        float ex = __expf(v - mx);
        g_alpha2[i] = ex;
        sum += ex;
    }
    g_rsum2[d] = 1.f / (sum + 1e-16f);
}

// ----- fused layer-2 aggregate + bias + log_softmax (warp per dst) ----------
__global__ void __launch_bounds__(256) k_agg2(const float* __restrict__ b2,
                                              float* __restrict__ out, int n) {
    int d = (blockIdx.x * blockDim.x + threadIdx.x) >> 5;
    int lane = threadIdx.x & 31;
    if (d >= n) return;
    int beg = g_rowstart[d], end = g_rowstart[d + 1];
    float acc = 0.f;
    for (int i = beg; i < end; i++) {
        int s = g_col[i];
        acc += g_h2[(size_t)s * 32 + lane] * g_alpha2[i];
    }
    float val = acc * g_rsum2[d] + b2[lane];
    float m2 = val;
    #pragma unroll
    for (int off = 16; off >= 1; off >>= 1)
        m2 = fmaxf(m2, __shfl_xor_sync(0xffffffffu, m2, off));
    float ex = __expf(val - m2);
    float s2 = ex;
    #pragma unroll
    for (int off = 16; off >= 1; off >>= 1)
        s2 += __shfl_xor_sync(0xffffffffu, s2, off);
    out[(size_t)d * 32 + lane] = val - m2 - logf(s2);
}

// ---------------- launch -----------------------------------------------------
extern "C" void kernel_launch(void* const* d_in, const int* in_sizes, int n_in,
                              void* d_out, int out_size) {
    const float* x    = (const float*)d_in[0];
    const int*   ei   = (const int*)d_in[1];
    const float* W1   = (const float*)d_in[2];
    const float* as1  = (const float*)d_in[3];
    const float* ad1  = (const float*)d_in[4];
    const float* b1   = (const float*)d_in[5];
    const float* W2   = (const float*)d_in[6];
    const float* as2  = (const float*)d_in[7];
    const float* ad2  = (const float*)d_in[8];
    const float* b2   = (const float*)d_in[9];
    float* out = (float*)d_out;

    int n = in_sizes[0] / FIN;
    int E = in_sizes[1] / 2;
    int etot = E + n;

    k_deg_init<<<(n + 255) / 256, 256>>>(n);
    k_count<<<(E + 255) / 256, 256>>>(ei, E);
    k_scan<<<1, 1024>>>(n);
    k_scatter<<<(etot + 255) / 256, 256>>>(ei, E, etot);

    k_prep_x<<<(n * 256 + 255) / 256, 256>>>(x, n * 256);
    k_prep_w<<<(256 * 256 + 255) / 256, 256>>>(W1);

    dim3 g1(2, (n + 127) / 128);
    k_gemm1_mma<<<g1, 256>>>(n);

    k_attn1<<<(n + 7) / 8, 256>>>(as1, ad1, n);
    k_alpha1<<<(n * 4 + 255) / 256, 256>>>(n);
    k_agg1<<<n, 256>>>(b1);

    dim3 g2(1, (n + G2_BM - 1) / G2_BM);
    k_gemm2<<<g2, 256>>>(W2, n);

    k_attn2<<<(n + 7) / 8, 256>>>(as2, ad2, n);
    k_alpha2<<<(n + 255) / 256, 256>>>(n);
    k_agg2<<<(n * 32 + 255) / 256, 256>>>(b2, out, n);
}

// round 10
// speedup vs baseline: 2.1062x; 1.0385x over previous
#include <cuda_runtime.h>
#include <cuda_bf16.h>
#include <math.h>
#include <stdint.h>

#define NN    50000
#define EE    800000
#define FIN   256
#define ETOT  (EE + NN)
#define NEG_SLOPE 0.2f

// ---------------- scratch (device globals) ----------------------------------
__device__ float g_h1[NN * 256];      // layer-1 linear output [N,4,64]
__device__ float g_as1[NN * 4];
__device__ float g_ad1[NN * 4];
__device__ float g_h2[NN * 32];       // layer-2 linear output
__device__ float g_as2[NN];
__device__ float g_ad2[NN];
__device__ float g_alpha1[ETOT * 4];  // unnormalized exp weight per CSR slot, head
__device__ float g_rsum1[NN * 4];     // 1/(sum+eps) per (dst, head)
__device__ float g_alpha2[ETOT];
__device__ float g_rsum2[NN];
// split-bf16 operands for tensor-core GEMMs
__device__ __nv_bfloat16 g_xhi[NN * 256];
__device__ __nv_bfloat16 g_xlo[NN * 256];
__device__ __nv_bfloat16 g_w1hi[256 * 256];   // [n][k] (transposed W1)
__device__ __nv_bfloat16 g_w1lo[256 * 256];
__device__ __nv_bfloat16 g_a2hi[NN * 256];    // relu(agg1+b1) split
__device__ __nv_bfloat16 g_a2lo[NN * 256];
__device__ __nv_bfloat16 g_w2hi[32 * 256];    // [n][k] (transposed W2)
__device__ __nv_bfloat16 g_w2lo[32 * 256];
// CSR (dst-bucketed incoming edges; slot stores src node id)
__device__ int   g_deg[NN];
__device__ int   g_rowstart[NN + 1];
__device__ int   g_col[ETOT];

// ---------------- CSR build --------------------------------------------------
__global__ void k_deg_init(int n) {
    int i = blockIdx.x * blockDim.x + threadIdx.x;
    if (i < n) g_deg[i] = 1;
}
__global__ void k_count(const int* __restrict__ ei, int E) {
    int e = blockIdx.x * blockDim.x + threadIdx.x;
    if (e < E) atomicAdd(&g_deg[ei[E + e]], 1);
}
__global__ void k_scan(int n) {
    __shared__ int sh[1024];
    int tid = threadIdx.x;
    int chunk = (n + 1023) / 1024;
    int beg = tid * chunk;
    int end = min(beg + chunk, n);
    int s = 0;
    for (int i = beg; i < end; i++) s += g_deg[i];
    sh[tid] = s;
    __syncthreads();
    #pragma unroll
    for (int off = 1; off < 1024; off <<= 1) {
        int v = (tid >= off) ? sh[tid - off] : 0;
        __syncthreads();
        sh[tid] += v;
        __syncthreads();
    }
    int run = (tid == 0) ? 0 : sh[tid - 1];
    for (int i = beg; i < end; i++) {
        int c = g_deg[i];
        g_rowstart[i] = run;
        g_deg[i] = run;
        run += c;
    }
    if (tid == 0) g_rowstart[n] = sh[1023];
}
__global__ void k_scatter(const int* __restrict__ ei, int E, int etot) {
    int e = blockIdx.x * blockDim.x + threadIdx.x;
    if (e >= etot) return;
    int s, d;
    if (e < E) { s = ei[e]; d = ei[E + e]; }
    else       { s = d = e - E; }
    int pos = atomicAdd(&g_deg[d], 1);
    g_col[pos] = s;
}

// ---------------- split-bf16 prep -------------------------------------------
__global__ void k_prep_x(const float* __restrict__ x, int total) {
    int i = blockIdx.x * blockDim.x + threadIdx.x;
    if (i >= total) return;
    float f = x[i];
    __nv_bfloat16 hi = __float2bfloat16_rn(f);
    g_xhi[i] = hi;
    g_xlo[i] = __float2bfloat16_rn(f - __bfloat162float(hi));
}
__global__ void k_prep_w(const float* __restrict__ W1) {
    int i = blockIdx.x * blockDim.x + threadIdx.x;
    if (i >= 256 * 256) return;
    int n = i >> 8, k = i & 255;
    float f = W1[k * 256 + n];
    __nv_bfloat16 hi = __float2bfloat16_rn(f);
    g_w1hi[i] = hi;
    g_w1lo[i] = __float2bfloat16_rn(f - __bfloat162float(hi));
}
__global__ void k_prep_w2(const float* __restrict__ W2) {
    int i = blockIdx.x * blockDim.x + threadIdx.x;
    if (i >= 32 * 256) return;
    int n = i >> 8, k = i & 255;
    float f = W2[k * 32 + n];
    __nv_bfloat16 hi = __float2bfloat16_rn(f);
    g_w2hi[i] = hi;
    g_w2lo[i] = __float2bfloat16_rn(f - __bfloat162float(hi));
}

// ---------------- mma.sync helper -------------------------------------------
#define PAD_K 40          // 32 + 8 bf16 padding -> 80-byte rows (16B aligned)
__device__ __forceinline__ void mma16816(float* c, const uint32_t* a, const uint32_t* b) {
    asm volatile(
        "mma.sync.aligned.m16n8k16.row.col.f32.bf16.bf16.f32 "
        "{%0,%1,%2,%3}, {%4,%5,%6,%7}, {%8,%9}, {%0,%1,%2,%3};"
        : "+f"(c[0]), "+f"(c[1]), "+f"(c[2]), "+f"(c[3])
        : "r"(a[0]), "r"(a[1]), "r"(a[2]), "r"(a[3]), "r"(b[0]), "r"(b[1]));
}

// ---------------- GEMM1 via mma.sync bf16 (split hi/lo) ---------------------
// CTA tile 128x128, K chunks of 32; 8 warps (4 M x 2 N), warp tile 32x64.
__global__ void __launch_bounds__(256) k_gemm1_mma(int M) {
    __shared__ __nv_bfloat16 sAhi[128 * PAD_K];
    __shared__ __nv_bfloat16 sAlo[128 * PAD_K];
    __shared__ __nv_bfloat16 sBhi[128 * PAD_K];
    __shared__ __nv_bfloat16 sBlo[128 * PAD_K];

    int tid = threadIdx.x;
    int wid = tid >> 5, lane = tid & 31;
    int wm = wid >> 1, wn = wid & 1;          // 4 x 2 warps
    int row0 = blockIdx.y * 128;
    int col0 = blockIdx.x * 128;

    float acc[2][8][4] = {};

    int lq = lane & 3;
    int lr = lane >> 2;

    for (int kc = 0; kc < 256; kc += 32) {
        #pragma unroll
        for (int i = 0; i < 2; i++) {
            int slot = tid + i * 256;
            int r = slot >> 2, q = slot & 3;
            int gr = row0 + r;
            uint4 vh = make_uint4(0, 0, 0, 0), vl = make_uint4(0, 0, 0, 0);
            if (gr < M) {
                vh = *(const uint4*)(g_xhi + (size_t)gr * 256 + kc + q * 8);
                vl = *(const uint4*)(g_xlo + (size_t)gr * 256 + kc + q * 8);
            }
            *(uint4*)(sAhi + r * PAD_K + q * 8) = vh;
            *(uint4*)(sAlo + r * PAD_K + q * 8) = vl;
        }
        #pragma unroll
        for (int i = 0; i < 2; i++) {
            int slot = tid + i * 256;
            int r = slot >> 2, q = slot & 3;
            int gn = col0 + r;
            *(uint4*)(sBhi + r * PAD_K + q * 8) = *(const uint4*)(g_w1hi + (size_t)gn * 256 + kc + q * 8);
            *(uint4*)(sBlo + r * PAD_K + q * 8) = *(const uint4*)(g_w1lo + (size_t)gn * 256 + kc + q * 8);
        }
        __syncthreads();

        #pragma unroll
        for (int ks = 0; ks < 2; ks++) {
            int kb = ks * 16;
            uint32_t ahi[2][4], alo[2][4], bhi[8][2], blo[8][2];
            #pragma unroll
            for (int mt = 0; mt < 2; mt++) {
                int rbase = wm * 32 + mt * 16;
                const __nv_bfloat16* p0h = sAhi + (rbase + lr) * PAD_K + kb + lq * 2;
                const __nv_bfloat16* p1h = sAhi + (rbase + 8 + lr) * PAD_K + kb + lq * 2;
                const __nv_bfloat16* p0l = sAlo + (rbase + lr) * PAD_K + kb + lq * 2;
                const __nv_bfloat16* p1l = sAlo + (rbase + 8 + lr) * PAD_K + kb + lq * 2;
                ahi[mt][0] = *(const uint32_t*)p0h;
                ahi[mt][1] = *(const uint32_t*)p1h;
                ahi[mt][2] = *(const uint32_t*)(p0h + 8);
                ahi[mt][3] = *(const uint32_t*)(p1h + 8);
                alo[mt][0] = *(const uint32_t*)p0l;
                alo[mt][1] = *(const uint32_t*)p1l;
                alo[mt][2] = *(const uint32_t*)(p0l + 8);
                alo[mt][3] = *(const uint32_t*)(p1l + 8);
            }
            #pragma unroll
            for (int nt = 0; nt < 8; nt++) {
                int nbase = wn * 64 + nt * 8;
                const __nv_bfloat16* ph = sBhi + (nbase + lr) * PAD_K + kb + lq * 2;
                const __nv_bfloat16* pl = sBlo + (nbase + lr) * PAD_K + kb + lq * 2;
                bhi[nt][0] = *(const uint32_t*)ph;
                bhi[nt][1] = *(const uint32_t*)(ph + 8);
                blo[nt][0] = *(const uint32_t*)pl;
                blo[nt][1] = *(const uint32_t*)(pl + 8);
            }
            #pragma unroll
            for (int mt = 0; mt < 2; mt++)
                #pragma unroll
                for (int nt = 0; nt < 8; nt++) {
                    mma16816(acc[mt][nt], ahi[mt], bhi[nt]);
                    mma16816(acc[mt][nt], ahi[mt], blo[nt]);
                    mma16816(acc[mt][nt], alo[mt], bhi[nt]);
                }
        }
        __syncthreads();
    }

    #pragma unroll
    for (int mt = 0; mt < 2; mt++) {
        int r0 = row0 + wm * 32 + mt * 16 + lr;
        #pragma unroll
        for (int nt = 0; nt < 8; nt++) {
            int c = col0 + wn * 64 + nt * 8 + lq * 2;
            if (r0 < M)
                *(float2*)(g_h1 + (size_t)r0 * 256 + c) = make_float2(acc[mt][nt][0], acc[mt][nt][1]);
            if (r0 + 8 < M)
                *(float2*)(g_h1 + (size_t)(r0 + 8) * 256 + c) = make_float2(acc[mt][nt][2], acc[mt][nt][3]);
        }
    }
}

// ---------------- attention dots, layer 1 (warp per node) -------------------
__global__ void k_attn1(const float* __restrict__ att_src, const float* __restrict__ att_dst, int n) {
    int warp = (blockIdx.x * blockDim.x + threadIdx.x) >> 5;
    int lane = threadIdx.x & 31;
    if (warp >= n) return;
    const float4* hr = (const float4*)(g_h1 + (size_t)warp * 256);
    const float4* sa = (const float4*)att_src;
    const float4* da = (const float4*)att_dst;
    float4 v0 = hr[lane], v1 = hr[lane + 32];
    float4 s0 = sa[lane], s1 = sa[lane + 32];
    float4 d0 = da[lane], d1 = da[lane + 32];
    float ps0 = v0.x*s0.x + v0.y*s0.y + v0.z*s0.z + v0.w*s0.w;
    float ps1 = v1.x*s1.x + v1.y*s1.y + v1.z*s1.z + v1.w*s1.w;
    float pd0 = v0.x*d0.x + v0.y*d0.y + v0.z*d0.z + v0.w*d0.w;
    float pd1 = v1.x*d1.x + v1.y*d1.y + v1.z*d1.z + v1.w*d1.w;
    #pragma unroll
    for (int off = 1; off < 16; off <<= 1) {
        ps0 += __shfl_xor_sync(0xffffffffu, ps0, off);
        ps1 += __shfl_xor_sync(0xffffffffu, ps1, off);
        pd0 += __shfl_xor_sync(0xffffffffu, pd0, off);
        pd1 += __shfl_xor_sync(0xffffffffu, pd1, off);
    }
    if (lane == 0)  { g_as1[warp*4+0] = ps0; g_as1[warp*4+2] = ps1;
                      g_ad1[warp*4+0] = pd0; g_ad1[warp*4+2] = pd1; }
    if (lane == 16) { g_as1[warp*4+1] = ps0; g_as1[warp*4+3] = ps1;
                      g_ad1[warp*4+1] = pd0; g_ad1[warp*4+3] = pd1; }
}

// ---------------- alpha precompute, layer 1 (thread per dst,head) -----------
__global__ void k_alpha1(int n) {
    int idx = blockIdx.x * blockDim.x + threadIdx.x;
    if (idx >= n * 4) return;
    int d = idx >> 2, h = idx & 3;
    int beg = g_rowstart[d], end = g_rowstart[d + 1];
    float adv = g_ad1[d * 4 + h];
    float mx = -3.4e38f;
    for (int i = beg; i < end; i++) {
        float v = __ldg(&g_as1[__ldg(&g_col[i]) * 4 + h]) + adv;
        v = (v > 0.f) ? v : NEG_SLOPE * v;
        mx = fmaxf(mx, v);
    }
    float sum = 0.f;
    for (int i = beg; i < end; i++) {
        float v = __ldg(&g_as1[__ldg(&g_col[i]) * 4 + h]) + adv;
        v = (v > 0.f) ? v : NEG_SLOPE * v;
        float ex = __expf(v - mx);
        g_alpha1[i * 4 + h] = ex;
        sum += ex;
    }
    g_rsum1[d * 4 + h] = 1.f / (sum + 1e-16f);
}

// --- fused layer-1 aggregate + bias + relu -> split bf16 (block per dst) ----
__global__ void __launch_bounds__(256) k_agg1(const float* __restrict__ b1) {
    int d = blockIdx.x;
    int tid = threadIdx.x;
    int h = tid >> 6;
    int beg = g_rowstart[d], end = g_rowstart[d + 1];
    float acc = 0.f;
    int i = beg;
    for (; i + 1 < end; i += 2) {
        int s0 = __ldg(&g_col[i]);
        int s1 = __ldg(&g_col[i + 1]);
        float w0 = __ldg(&g_alpha1[i * 4 + h]);
        float w1 = __ldg(&g_alpha1[(i + 1) * 4 + h]);
        float v0 = __ldg(&g_h1[(size_t)s0 * 256 + tid]);
        float v1 = __ldg(&g_h1[(size_t)s1 * 256 + tid]);
        acc += v0 * w0 + v1 * w1;
    }
    if (i < end) {
        int s0 = __ldg(&g_col[i]);
        acc += __ldg(&g_h1[(size_t)s0 * 256 + tid]) * __ldg(&g_alpha1[i * 4 + h]);
    }
    float val = acc * g_rsum1[d * 4 + h] + b1[tid];
    val = fmaxf(val, 0.f);
    __nv_bfloat16 hi = __float2bfloat16_rn(val);
    g_a2hi[(size_t)d * 256 + tid] = hi;
    g_a2lo[(size_t)d * 256 + tid] = __float2bfloat16_rn(val - __bfloat162float(hi));
}

// ---------------- GEMM2 via mma.sync bf16 (split hi/lo) ---------------------
// CTA tile 128x32, 8 warps (8 M x 1 N), warp tile 16x32; K chunks of 32.
__global__ void __launch_bounds__(256) k_gemm2_mma(int M) {
    __shared__ __nv_bfloat16 sAhi[128 * PAD_K];
    __shared__ __nv_bfloat16 sAlo[128 * PAD_K];
    __shared__ __nv_bfloat16 sBhi[32 * PAD_K];
    __shared__ __nv_bfloat16 sBlo[32 * PAD_K];

    int tid = threadIdx.x;
    int wid = tid >> 5, lane = tid & 31;
    int row0 = blockIdx.x * 128;
    int lq = lane & 3;
    int lr = lane >> 2;

    float acc[4][4] = {};

    for (int kc = 0; kc < 256; kc += 32) {
        #pragma unroll
        for (int i = 0; i < 2; i++) {
            int slot = tid + i * 256;
            int r = slot >> 2, q = slot & 3;
            int gr = row0 + r;
            uint4 vh = make_uint4(0, 0, 0, 0), vl = make_uint4(0, 0, 0, 0);
            if (gr < M) {
                vh = *(const uint4*)(g_a2hi + (size_t)gr * 256 + kc + q * 8);
                vl = *(const uint4*)(g_a2lo + (size_t)gr * 256 + kc + q * 8);
            }
            *(uint4*)(sAhi + r * PAD_K + q * 8) = vh;
            *(uint4*)(sAlo + r * PAD_K + q * 8) = vl;
        }
        if (tid < 128) {
            int r = tid >> 2, q = tid & 3;
            *(uint4*)(sBhi + r * PAD_K + q * 8) = *(const uint4*)(g_w2hi + (size_t)r * 256 + kc + q * 8);
            *(uint4*)(sBlo + r * PAD_K + q * 8) = *(const uint4*)(g_w2lo + (size_t)r * 256 + kc + q * 8);
        }
        __syncthreads();

        #pragma unroll
        for (int ks = 0; ks < 2; ks++) {
            int kb = ks * 16;
            uint32_t ahi[4], alo[4], bhi[4][2], blo[4][2];
            int rbase = wid * 16;
            const __nv_bfloat16* p0h = sAhi + (rbase + lr) * PAD_K + kb + lq * 2;
            const __nv_bfloat16* p1h = sAhi + (rbase + 8 + lr) * PAD_K + kb + lq * 2;
            const __nv_bfloat16* p0l = sAlo + (rbase + lr) * PAD_K + kb + lq * 2;
            const __nv_bfloat16* p1l = sAlo + (rbase + 8 + lr) * PAD_K + kb + lq * 2;
            ahi[0] = *(const uint32_t*)p0h;
            ahi[1] = *(const uint32_t*)p1h;
            ahi[2] = *(const uint32_t*)(p0h + 8);
            ahi[3] = *(const uint32_t*)(p1h + 8);
            alo[0] = *(const uint32_t*)p0l;
            alo[1] = *(const uint32_t*)p1l;
            alo[2] = *(const uint32_t*)(p0l + 8);
            alo[3] = *(const uint32_t*)(p1l + 8);
            #pragma unroll
            for (int nt = 0; nt < 4; nt++) {
                int nbase = nt * 8;
                const __nv_bfloat16* ph = sBhi + (nbase + lr) * PAD_K + kb + lq * 2;
                const __nv_bfloat16* pl = sBlo + (nbase + lr) * PAD_K + kb + lq * 2;
                bhi[nt][0] = *(const uint32_t*)ph;
                bhi[nt][1] = *(const uint32_t*)(ph + 8);
                blo[nt][0] = *(const uint32_t*)pl;
                blo[nt][1] = *(const uint32_t*)(pl + 8);
            }
            #pragma unroll
            for (int nt = 0; nt < 4; nt++) {
                mma16816(acc[nt], ahi, bhi[nt]);
                mma16816(acc[nt], ahi, blo[nt]);
                mma16816(acc[nt], alo, bhi[nt]);
            }
        }
        __syncthreads();
    }

    int r0 = row0 + wid * 16 + lr;
    #pragma unroll
    for (int nt = 0; nt < 4; nt++) {
        int c = nt * 8 + lq * 2;
        if (r0 < M)
            *(float2*)(g_h2 + (size_t)r0 * 32 + c) = make_float2(acc[nt][0], acc[nt][1]);
        if (r0 + 8 < M)
            *(float2*)(g_h2 + (size_t)(r0 + 8) * 32 + c) = make_float2(acc[nt][2], acc[nt][3]);
    }
}

// ---------------- attention dots, layer 2 (warp per node) -------------------
__global__ void k_attn2(const float* __restrict__ att_src, const float* __restrict__ att_dst, int n) {
    int warp = (blockIdx.x * blockDim.x + threadIdx.x) >> 5;
    int lane = threadIdx.x & 31;
    if (warp >= n) return;
    float v = g_h2[(size_t)warp * 32 + lane];
    float ps = v * att_src[lane];
    float pd = v * att_dst[lane];
    #pragma unroll
    for (int off = 16; off >= 1; off >>= 1) {
        ps += __shfl_xor_sync(0xffffffffu, ps, off);
        pd += __shfl_xor_sync(0xffffffffu, pd, off);
    }
    if (lane == 0) { g_as2[warp] = ps; g_ad2[warp] = pd; }
}

// ---------------- alpha precompute, layer 2 (thread per dst) ----------------
__global__ void k_alpha2(int n) {
    int d = blockIdx.x * blockDim.x + threadIdx.x;
    if (d >= n) return;
    int beg = g_rowstart[d], end = g_rowstart[d + 1];
    float adv = g_ad2[d];
    float mx = -3.4e38f;
    for (int i = beg; i < end; i++) {
        float v = __ldg(&g_as2[__ldg(&g_col[i])]) + adv;
        v = (v > 0.f) ? v : NEG_SLOPE * v;
        mx = fmaxf(mx, v);
    }
    float sum = 0.f;
    for (int i = beg; i < end; i++) {
        float v = __ldg(&g_as2[__ldg(&g_col[i])]) + adv;
        v = (v > 0.f) ? v : NEG_SLOPE * v;
        float ex = __expf(v - mx);
        g_alpha2[i] = ex;
        sum += ex;
    }
    g_rsum2[d] = 1.f / (sum + 1e-16f);
}

// ----- fused layer-2 aggregate + bias + log_softmax (warp per dst) ----------
__global__ void __launch_bounds__(256) k_agg2(const float* __restrict__ b2,
                                              float* __restrict__ out, int n) {
    int d = (blockIdx.x * blockDim.x + threadIdx.x) >> 5;
    int lane = threadIdx.x & 31;
    if (d >= n) return;
    int beg = g_rowstart[d], end = g_rowstart[d + 1];
    float acc = 0.f;
    int i = beg;
    for (; i + 1 < end; i += 2) {
        int s0 = __ldg(&g_col[i]);
        int s1 = __ldg(&g_col[i + 1]);
        float w0 = __ldg(&g_alpha2[i]);
        float w1 = __ldg(&g_alpha2[i + 1]);
        acc += __ldg(&g_h2[(size_t)s0 * 32 + lane]) * w0
             + __ldg(&g_h2[(size_t)s1 * 32 + lane]) * w1;
    }
    if (i < end) {
        int s0 = __ldg(&g_col[i]);
        acc += __ldg(&g_h2[(size_t)s0 * 32 + lane]) * __ldg(&g_alpha2[i]);
    }
    float val = acc * g_rsum2[d] + b2[lane];
    float m2 = val;
    #pragma unroll
    for (int off = 16; off >= 1; off >>= 1)
        m2 = fmaxf(m2, __shfl_xor_sync(0xffffffffu, m2, off));
    float ex = __expf(val - m2);
    float s2 = ex;
    #pragma unroll
    for (int off = 16; off >= 1; off >>= 1)
        s2 += __shfl_xor_sync(0xffffffffu, s2, off);
    out[(size_t)d * 32 + lane] = val - m2 - logf(s2);
}

// ---------------- launch -----------------------------------------------------
extern "C" void kernel_launch(void* const* d_in, const int* in_sizes, int n_in,
                              void* d_out, int out_size) {
    const float* x    = (const float*)d_in[0];
    const int*   ei   = (const int*)d_in[1];
    const float* W1   = (const float*)d_in[2];
    const float* as1  = (const float*)d_in[3];
    const float* ad1  = (const float*)d_in[4];
    const float* b1   = (const float*)d_in[5];
    const float* W2   = (const float*)d_in[6];
    const float* as2  = (const float*)d_in[7];
    const float* ad2  = (const float*)d_in[8];
    const float* b2   = (const float*)d_in[9];
    float* out = (float*)d_out;

    int n = in_sizes[0] / FIN;
    int E = in_sizes[1] / 2;
    int etot = E + n;

    k_deg_init<<<(n + 255) / 256, 256>>>(n);
    k_count<<<(E + 255) / 256, 256>>>(ei, E);
    k_scan<<<1, 1024>>>(n);
    k_scatter<<<(etot + 255) / 256, 256>>>(ei, E, etot);

    k_prep_x<<<(n * 256 + 255) / 256, 256>>>(x, n * 256);
    k_prep_w<<<(256 * 256 + 255) / 256, 256>>>(W1);
    k_prep_w2<<<(32 * 256 + 255) / 256, 256>>>(W2);

    dim3 g1(2, (n + 127) / 128);
    k_gemm1_mma<<<g1, 256>>>(n);

    k_attn1<<<(n + 7) / 8, 256>>>(as1, ad1, n);
    k_alpha1<<<(n * 4 + 255) / 256, 256>>>(n);
    k_agg1<<<n, 256>>>(b1);

    k_gemm2_mma<<<(n + 127) / 128, 256>>>(n);

    k_attn2<<<(n + 7) / 8, 256>>>(as2, ad2, n);
    k_alpha2<<<(n + 255) / 256, 256>>>(n);
    k_agg2<<<(n * 32 + 255) / 256, 256>>>(b2, out, n);
}